// round 14
// baseline (speedup 1.0000x reference)
#include <cuda_runtime.h>
#include <cuda_bf16.h>
#include <cstdint>

#define HWN 4096
#define BBN 4

// ---------------- static scratch (packed {bf16hi,bf16lo} u32) ---------------
__device__ uint32_t g_xp [(size_t)BBN * 1024 * HWN];
__device__ uint32_t g_h1 [(size_t)BBN * 1024 * HWN];
__device__ uint32_t g_h2 [(size_t)BBN * 256  * HWN];
__device__ uint32_t g_h3 [(size_t)BBN * 256  * HWN];
__device__ uint32_t g_h4 [(size_t)BBN * 256  * HWN];
__device__ uint32_t g_h5 [(size_t)BBN * 256  * HWN];
__device__ uint32_t g_wo1[(size_t)2048 * 9 * 1024];
__device__ uint32_t g_w1 [(size_t)256  * 1024];
__device__ uint32_t g_wo2[(size_t)512  * 9 * 256];
__device__ uint32_t g_w2 [(size_t)256  * 9 * 256];
__device__ uint32_t g_wo3[(size_t)512  * 9 * 256];
__device__ uint32_t g_w3 [(size_t)1024 * 256];
__device__ float g_sc1[256],  g_bi1[256];
__device__ float g_sc2[256],  g_bi2[256];
__device__ float g_sc3[1024], g_bi3[1024];

// ---------------- helpers ----------------------------------------------------
__device__ __forceinline__ uint32_t packbf(float x) {
    __nv_bfloat16 h = __float2bfloat16(x);
    float hf = __bfloat162float(h);
    __nv_bfloat16 l = __float2bfloat16(x - hf);
    return ((uint32_t)__bfloat16_as_ushort(h) << 16) | (uint32_t)__bfloat16_as_ushort(l);
}
__device__ __forceinline__ float unpackbf(uint32_t p) {
    return __uint_as_float(p & 0xffff0000u) + __uint_as_float(p << 16);
}
__device__ __forceinline__ uint32_t prmt(uint32_t a, uint32_t b, uint32_t s) {
    uint32_t r; asm("prmt.b32 %0, %1, %2, %3;" : "=r"(r) : "r"(a), "r"(b), "r"(s)); return r;
}
__device__ __forceinline__ uint32_t cvta_smem(const void* p) {
    uint32_t a;
    asm("{ .reg .u64 t; cvta.to.shared.u64 t, %1; cvt.u32.u64 %0, t; }" : "=r"(a) : "l"(p));
    return a;
}

// m16n8k16 bf16 MMA, f32 accumulate (sm_80+ PTX: compiles in both passes).
#define MMA_BF16(c, a, b) \
    asm volatile("mma.sync.aligned.m16n8k16.row.col.f32.bf16.bf16.f32 " \
        "{%0,%1,%2,%3}, {%4,%5,%6,%7}, {%8,%9}, {%0,%1,%2,%3};" \
        : "+f"((c)[0]), "+f"((c)[1]), "+f"((c)[2]), "+f"((c)[3]) \
        : "r"((a)[0]), "r"((a)[1]), "r"((a)[2]), "r"((a)[3]), \
          "r"((b)[0]), "r"((b)[1]))

// ldmatrix x4 (sm_75+): 4x 8x8 b16 tiles, address per lane.
#define LDSM_X4(R0, R1, R2, R3, A) \
    asm volatile("ldmatrix.sync.aligned.m8n8.x4.shared.b16 {%0,%1,%2,%3}, [%4];" \
        : "=r"(R0), "=r"(R1), "=r"(R2), "=r"(R3) : "r"(A))

// ---------------- prep kernels (fused: exactly 5 launches pre-stage1) -------
__global__ void prep_bn_all(const float* g1, const float* b1, const float* m1, const float* v1,
                            const float* g2, const float* b2, const float* m2, const float* v2,
                            const float* g3, const float* b3, const float* m3, const float* v3,
                            float* sc1, float* bi1, float* sc2, float* bi2,
                            float* sc3, float* bi3) {
    int i = blockIdx.x * blockDim.x + threadIdx.x;
    if (i < 256) {
        float inv = g1[i] * rsqrtf(v1[i] + 1e-5f);
        sc1[i] = inv; bi1[i] = b1[i] - m1[i] * inv;
    } else if (i < 512) {
        int c = i - 256;
        float inv = g2[c] * rsqrtf(v2[c] + 1e-5f);
        sc2[c] = inv; bi2[c] = b2[c] - m2[c] * inv;
    } else if (i < 1536) {
        int c = i - 512;
        float inv = g3[c] * rsqrtf(v3[c] + 1e-5f);
        sc3[c] = inv; bi3[c] = b3[c] - m3[c] * inv;
    }
}
__global__ void xprep_kernel(const float* __restrict__ x, uint32_t* __restrict__ xp, int n) {
    int i = blockIdx.x * blockDim.x + threadIdx.x;
    if (i < n) xp[i] = packbf(x[i]);
}
// [Cout][Cin][TAPS] -> packed [oc][tap][ic]
__device__ __forceinline__ void wprep_one(const float* w, uint32_t* wp, int Cin, int TAPS, int i) {
    int ct = Cin * TAPS;
    int oc = i / ct;
    int r  = i - oc * ct;
    int ic = r / TAPS;
    int t  = r - ic * TAPS;
    wp[((size_t)oc * TAPS + t) * Cin + ic] = packbf(w[i]);
}
__global__ void wprep_kernel(const float* __restrict__ w, uint32_t* __restrict__ wp,
                             int Cin, int TAPS, int n) {
    int i = blockIdx.x * blockDim.x + threadIdx.x;
    if (i < n) wprep_one(w, wp, Cin, TAPS, i);
}
__global__ void wprep_pair(const float* wa, uint32_t* wpa, const float* wb, uint32_t* wpb,
                           int Cin, int TAPS, int half) {
    int i = blockIdx.x * blockDim.x + threadIdx.x;
    if (i < half)               wprep_one(wa, wpa, Cin, TAPS, i);
    else if (i < 2 * half)      wprep_one(wb, wpb, Cin, TAPS, i - half);
}
// BUGFIX (R12): explicit range bounds. Previous version's garbled middle bound
// (8520*97+262144 = 1,088,584) left the last ~25K elements of w3 unpacked ->
// ~10% of conv3's output channels used zero weights -> rel_err 0.30.
__global__ void wprep_trio(const float* w1, uint32_t* p1,   // 256x1024x1 : 262144
                           const float* w2, uint32_t* p2,   // 256x256x9  : 589824
                           const float* w3, uint32_t* p3) { // 1024x256x1 : 262144
    int i = blockIdx.x * blockDim.x + threadIdx.x;
    if (i < 262144)        wprep_one(w1, p1, 1024, 1, i);
    else if (i < 851968)   wprep_one(w2, p2, 256, 9, i - 262144);
    else if (i < 1114112)  wprep_one(w3, p3, 256, 1, i - 851968);
}

// ---------------- fused conv via mma.sync + ldmatrix -------------------------
// Tile: M=128 oc x N=128 px (2 image rows), K-chunk 64.
// 8 warps: warp w -> (mw=w&3) M-quadrant(32 oc), (nw=w>>2) N-half(64 px).
// Markidis bf16 split: acc += Ahi*Bhi + Ahi*Blo + Alo*Bhi.
// EPI: 0 deform(pack), 1 affine(pack), 2 affine+relu(f32).
static constexpr int DSMEM = 73728;

template<int TAPS, int EPI>
__global__ __launch_bounds__(256)
void mmaconv(const uint32_t* __restrict__ inp, const uint32_t* __restrict__ wp,
             const float* __restrict__ cbias,
             const float* __restrict__ sc, const float* __restrict__ bi,
             uint32_t* __restrict__ outp, float* __restrict__ outf,
             int Cin, int Cout)
{
    extern __shared__ uint32_t sm[];
    uint32_t* Ahi = sm;
    uint32_t* Alo = sm + 4608;
    uint32_t* Bhi = sm + 9216;
    uint32_t* Blo = sm + 13824;
    const uint32_t sb   = cvta_smem(sm);
    const uint32_t aAhi = sb;
    const uint32_t aAlo = sb + 4608u * 4u;
    const uint32_t aBhi = sb + 9216u * 4u;
    const uint32_t aBlo = sb + 13824u * 4u;

    const int tid  = threadIdx.x;
    const int w    = tid >> 5, lane = tid & 31;
    const int mw   = w & 3, nw = w >> 2;
    const int bimg = blockIdx.x >> 5;
    const int y0   = (blockIdx.x & 31) << 1;
    const int oc0  = blockIdx.y << 7;

    // ldmatrix per-lane geometry (hoisted):
    //  A x4 quads: [rows r0..7 @k0][rows r8..15 @k0][r0..7 @k+8][r8..15 @k+8]
    const int la7 = lane & 7;
    const int rA   = mw * 32 + la7 + ((lane >> 3) & 1) * 8;    // + mf*16
    const int cA   = (lane >> 4) * 4;                          // word offset
    //  B x4 quads: [n0..7 @k0][n0..7 @k+8][n8..15 @k0][n8..15 @k+8]
    const int rB   = nw * 64 + la7 + (lane >> 4) * 8;          // + nfp*16
    const int cB   = ((lane >> 3) & 1) * 4;

    float acc[2][8][4];
#pragma unroll
    for (int a = 0; a < 2; ++a)
#pragma unroll
        for (int b = 0; b < 8; ++b)
#pragma unroll
            for (int c = 0; c < 4; ++c) acc[a][b][c] = 0.f;

    const int n_chunks = TAPS * (Cin >> 6);
    for (int ch = 0; ch < n_chunks; ++ch) {
        const int tap = (TAPS == 9) ? (ch % 9) : 0;
        const int ic0 = ((TAPS == 9) ? (ch / 9) : ch) << 6;
        const int dyt = (TAPS == 9) ? (tap / 3 - 1) : 0;
        const int dxt = (TAPS == 9) ? (tap % 3 - 1) : 0;

        {   // stage A (weights): warp w -> oc rows w*16..+15, lane -> k-pair
            const uint32_t* wrow = wp + ((size_t)(oc0 + (w << 4)) * TAPS + tap) * Cin
                                      + ic0 + (lane << 1);
            const size_t rstride = (size_t)TAPS * Cin;
#pragma unroll 4
            for (int r = 0; r < 16; ++r) {
                uint2 p = *reinterpret_cast<const uint2*>(wrow + (size_t)r * rstride);
                int row = (w << 4) + r;
                Ahi[row * 36 + lane] = prmt(p.x, p.y, 0x7632u);
                Alo[row * 36 + lane] = prmt(p.x, p.y, 0x5410u);
            }
        }
        {   // stage B (pixels): B[n=px][k=ic], coalesced along px
            const uint32_t* ibase = inp + (size_t)bimg * Cin * HWN;
#pragma unroll
            for (int nb = 0; nb < 2; ++nb) {
                const int n  = (w << 4) + (nb << 3) + (lane & 7);
                const int gy = y0 + (n >> 6) + dyt;
                const int gx = (n & 63) + dxt;
                const bool ok = (TAPS == 1) ||
                                (((unsigned)gy < 64u) && ((unsigned)gx < 64u));
                const int gyc = ok ? gy : 0, gxc = ok ? gx : 0;
                const uint32_t* col = ibase + (size_t)(ic0 + ((lane >> 3) << 1)) * HWN
                                            + gyc * 64 + gxc;
#pragma unroll 4
                for (int m = 0; m < 8; ++m) {
                    const uint32_t* q = col + (size_t)(m << 3) * HWN;
                    uint32_t p0 = ok ? q[0]   : 0u;
                    uint32_t p1 = ok ? q[HWN] : 0u;
                    int pair = (lane >> 3) + (m << 2);
                    Bhi[n * 36 + pair] = prmt(p0, p1, 0x7632u);
                    Blo[n * 36 + pair] = prmt(p0, p1, 0x5410u);
                }
            }
        }
        __syncthreads();

#pragma unroll
        for (int ks = 0; ks < 4; ++ks) {
            uint32_t ah[2][4], al[2][4];
#pragma unroll
            for (int mf = 0; mf < 2; ++mf) {
                uint32_t off = (uint32_t)(((rA + mf * 16) * 36 + ks * 8 + cA) << 2);
                LDSM_X4(ah[mf][0], ah[mf][1], ah[mf][2], ah[mf][3], aAhi + off);
                LDSM_X4(al[mf][0], al[mf][1], al[mf][2], al[mf][3], aAlo + off);
            }
            uint32_t bh[8][2], bl[8][2];
#pragma unroll
            for (int nfp = 0; nfp < 4; ++nfp) {
                uint32_t off = (uint32_t)(((rB + nfp * 16) * 36 + ks * 8 + cB) << 2);
                LDSM_X4(bh[2 * nfp][0], bh[2 * nfp][1],
                        bh[2 * nfp + 1][0], bh[2 * nfp + 1][1], aBhi + off);
                LDSM_X4(bl[2 * nfp][0], bl[2 * nfp][1],
                        bl[2 * nfp + 1][0], bl[2 * nfp + 1][1], aBlo + off);
            }
#pragma unroll
            for (int mf = 0; mf < 2; ++mf)
#pragma unroll
                for (int nf = 0; nf < 8; ++nf) {
                    MMA_BF16(acc[mf][nf], ah[mf], bh[nf]);
                    MMA_BF16(acc[mf][nf], ah[mf], bl[nf]);
                    MMA_BF16(acc[mf][nf], al[mf], bh[nf]);
                }
        }
        __syncthreads();
    }

    // ---- stage D fragments to SMEM so the epilogue gets a clean (oc,px) view
    float* Ds = (float*)sm;     // [128][130] f32
#pragma unroll
    for (int mf = 0; mf < 2; ++mf)
#pragma unroll
        for (int nf = 0; nf < 8; ++nf) {
            int row = mw * 32 + mf * 16 + (lane >> 2);
            int col = nw * 64 + nf * 8 + 2 * (lane & 3);
            Ds[row * 130 + col]           = acc[mf][nf][0];
            Ds[row * 130 + col + 1]       = acc[mf][nf][1];
            Ds[(row + 8) * 130 + col]     = acc[mf][nf][2];
            Ds[(row + 8) * 130 + col + 1] = acc[mf][nf][3];
        }
    __syncthreads();

    const int tx = tid & 15, ty = tid >> 4;
    float a8[8][8];
#pragma unroll
    for (int i = 0; i < 8; ++i)
#pragma unroll
        for (int j = 0; j < 8; ++j)
            a8[i][j] = Ds[(ty * 8 + i) * 130 + tx * 8 + j];

    if (EPI == 0) {
        const int Cc  = Cout >> 1;
        const int ocb = oc0 + ty * 8;
#pragma unroll
        for (int t2 = 0; t2 < 4; t2++) {
            const int c = (ocb >> 1) + t2;
            const uint32_t* src = inp + (size_t)(bimg * Cin + c) * HWN;
            uint32_t* dst = outp + (size_t)(bimg * Cc + c) * HWN;
            float cby = cbias[ocb + 2 * t2], cbx = cbias[ocb + 2 * t2 + 1];
#pragma unroll
            for (int j = 0; j < 8; j++) {
                int p = tx * 8 + j, gy = y0 + (p >> 6), gx = p & 63;
                float dy = a8[2 * t2][j] + cby;
                float dx = a8[2 * t2 + 1][j] + cbx;
                float py = fminf(fmaxf((float)gy + dy, 0.f), 63.f);
                float px = fminf(fmaxf((float)gx + dx, 0.f), 63.f);
                float fy = floorf(py), fx = floorf(px);
                int iy0 = (int)fy, ix0 = (int)fx;
                int iy1 = min(iy0 + 1, 63), ix1 = min(ix0 + 1, 63);
                float wy = py - fy, wx = px - fx;
                float v00 = unpackbf(src[iy0 * 64 + ix0]), v01 = unpackbf(src[iy0 * 64 + ix1]);
                float v10 = unpackbf(src[iy1 * 64 + ix0]), v11 = unpackbf(src[iy1 * 64 + ix1]);
                float vt = v00 + (v01 - v00) * wx;
                float vb = v10 + (v11 - v10) * wx;
                dst[gy * 64 + gx] = packbf(vt + (vb - vt) * wy);
            }
        }
    } else {
#pragma unroll
        for (int i = 0; i < 8; i++) {
            int oc = oc0 + ty * 8 + i;
            float s = sc[oc], bo = bi[oc];
#pragma unroll
            for (int j = 0; j < 8; j++) {
                int p = tx * 8 + j, gy = y0 + (p >> 6), gx = p & 63;
                float v = a8[i][j] * s + bo;
                size_t o = (size_t)(bimg * Cout + oc) * HWN + gy * 64 + gx;
                if (EPI == 1) outp[o] = packbf(v);
                else          outf[o] = fmaxf(v, 0.f);
            }
        }
    }
}

// ---------------------------------------------------------------------------
extern "C" void kernel_launch(void* const* d_in, const int* in_sizes, int n_in,
                              void* d_out, int out_size)
{
    (void)n_in; (void)out_size;
    const float *x, *ow1, *ob1, *ow2, *ob2, *ow3, *ob3, *w1, *w2, *w3;
    const float *g1, *b1, *m1, *v1, *g2, *b2, *m2, *v2, *g3, *b3, *m3, *v3;
    x   = (const float*)d_in[0];
    ow1 = (const float*)d_in[1];
    ob1 = (const float*)d_in[2];
    if (in_sizes[3] == 262144) {   // signature order
        w1  = (const float*)d_in[3];
        g1  = (const float*)d_in[4];  b1 = (const float*)d_in[5];
        m1  = (const float*)d_in[6];  v1 = (const float*)d_in[7];
        ow2 = (const float*)d_in[8];  ob2 = (const float*)d_in[9];
        w2  = (const float*)d_in[10];
        g2  = (const float*)d_in[11]; b2 = (const float*)d_in[12];
        m2  = (const float*)d_in[13]; v2 = (const float*)d_in[14];
        ow3 = (const float*)d_in[15]; ob3 = (const float*)d_in[16];
        w3  = (const float*)d_in[17];
        g3  = (const float*)d_in[18]; b3 = (const float*)d_in[19];
        m3  = (const float*)d_in[20]; v3 = (const float*)d_in[21];
    } else {                        // setup_inputs dict order
        ow2 = (const float*)d_in[3];  ob2 = (const float*)d_in[4];
        ow3 = (const float*)d_in[5];  ob3 = (const float*)d_in[6];
        w1  = (const float*)d_in[7];
        w2  = (const float*)d_in[8];
        w3  = (const float*)d_in[9];
        g1  = (const float*)d_in[10]; b1 = (const float*)d_in[11];
        m1  = (const float*)d_in[12]; v1 = (const float*)d_in[13];
        g2  = (const float*)d_in[14]; b2 = (const float*)d_in[15];
        m2  = (const float*)d_in[16]; v2 = (const float*)d_in[17];
        g3  = (const float*)d_in[18]; b3 = (const float*)d_in[19];
        m3  = (const float*)d_in[20]; v3 = (const float*)d_in[21];
    }
    float* out = (float*)d_out;

    uint32_t *xp, *h1, *h2, *h3, *h4, *h5, *wo1, *wq1, *wo2, *wq2, *wo3, *wq3;
    float *sc1, *bi1, *sc2, *bi2, *sc3, *bi3;
    cudaGetSymbolAddress((void**)&xp,  g_xp);
    cudaGetSymbolAddress((void**)&h1,  g_h1);
    cudaGetSymbolAddress((void**)&h2,  g_h2);
    cudaGetSymbolAddress((void**)&h3,  g_h3);
    cudaGetSymbolAddress((void**)&h4,  g_h4);
    cudaGetSymbolAddress((void**)&h5,  g_h5);
    cudaGetSymbolAddress((void**)&wo1, g_wo1);
    cudaGetSymbolAddress((void**)&wq1, g_w1);
    cudaGetSymbolAddress((void**)&wo2, g_wo2);
    cudaGetSymbolAddress((void**)&wq2, g_w2);
    cudaGetSymbolAddress((void**)&wo3, g_wo3);
    cudaGetSymbolAddress((void**)&wq3, g_w3);
    cudaGetSymbolAddress((void**)&sc1, g_sc1);
    cudaGetSymbolAddress((void**)&bi1, g_bi1);
    cudaGetSymbolAddress((void**)&sc2, g_sc2);
    cudaGetSymbolAddress((void**)&bi2, g_bi2);
    cudaGetSymbolAddress((void**)&sc3, g_sc3);
    cudaGetSymbolAddress((void**)&bi3, g_bi3);

    cudaFuncSetAttribute(mmaconv<9,0>, cudaFuncAttributeMaxDynamicSharedMemorySize, DSMEM);
    cudaFuncSetAttribute(mmaconv<1,1>, cudaFuncAttributeMaxDynamicSharedMemorySize, DSMEM);
    cudaFuncSetAttribute(mmaconv<9,1>, cudaFuncAttributeMaxDynamicSharedMemorySize, DSMEM);
    cudaFuncSetAttribute(mmaconv<1,2>, cudaFuncAttributeMaxDynamicSharedMemorySize, DSMEM);

    // exactly 5 prep launches so ncu (-s 5 -c 1) profiles stage-1 mmaconv
    prep_bn_all<<<6, 256>>>(g1, b1, m1, v1, g2, b2, m2, v2, g3, b3, m3, v3,
                            sc1, bi1, sc2, bi2, sc3, bi3);
    { int n = BBN * 1024 * HWN; xprep_kernel<<<(n + 255) / 256, 256>>>(x, xp, n); }
    { int n = 2048 * 1024 * 9;  wprep_kernel<<<(n + 255) / 256, 256>>>(ow1, wo1, 1024, 9, n); }
    { int half = 512 * 256 * 9; int n = 2 * half;
      wprep_pair<<<(n + 255) / 256, 256>>>(ow2, wo2, ow3, wo3, 256, 9, half); }
    { int n = 1114112;          wprep_trio<<<(n + 255) / 256, 256>>>(w1, wq1, w2, wq2, w3, wq3); }

    const dim3 blk(256);
    mmaconv<9,0><<<dim3(128, 16), blk, DSMEM>>>(xp, wo1, ob1, nullptr, nullptr, h1, nullptr, 1024, 2048);
    mmaconv<1,1><<<dim3(128, 2),  blk, DSMEM>>>(h1, wq1, nullptr, sc1, bi1, h2, nullptr, 1024, 256);
    mmaconv<9,0><<<dim3(128, 4),  blk, DSMEM>>>(h2, wo2, ob2, nullptr, nullptr, h3, nullptr, 256, 512);
    mmaconv<9,1><<<dim3(128, 2),  blk, DSMEM>>>(h3, wq2, nullptr, sc2, bi2, h4, nullptr, 256, 256);
    mmaconv<9,0><<<dim3(128, 4),  blk, DSMEM>>>(h4, wo3, ob3, nullptr, nullptr, h5, nullptr, 256, 512);
    mmaconv<1,2><<<dim3(128, 8),  blk, DSMEM>>>(h5, wq3, nullptr, sc3, bi3, nullptr, out, 256, 1024);
}

// round 15
// speedup vs baseline: 1.4079x; 1.4079x over previous
#include <cuda_runtime.h>
#include <cuda_bf16.h>
#include <cstdint>

#define HWN 4096
#define BBN 4

// ---------------- static scratch (packed {bf16hi,bf16lo} u32) ---------------
__device__ uint32_t g_xp [(size_t)BBN * 1024 * HWN];
__device__ uint32_t g_h1 [(size_t)BBN * 1024 * HWN];
__device__ uint32_t g_h2 [(size_t)BBN * 256  * HWN];
__device__ uint32_t g_h3 [(size_t)BBN * 256  * HWN];
__device__ uint32_t g_h4 [(size_t)BBN * 256  * HWN];
__device__ uint32_t g_h5 [(size_t)BBN * 256  * HWN];
__device__ uint32_t g_wo1[(size_t)2048 * 9 * 1024];
__device__ uint32_t g_w1 [(size_t)256  * 1024];
__device__ uint32_t g_wo2[(size_t)512  * 9 * 256];
__device__ uint32_t g_w2 [(size_t)256  * 9 * 256];
__device__ uint32_t g_wo3[(size_t)512  * 9 * 256];
__device__ uint32_t g_w3 [(size_t)1024 * 256];
__device__ float g_sc1[256],  g_bi1[256];
__device__ float g_sc2[256],  g_bi2[256];
__device__ float g_sc3[1024], g_bi3[1024];

// ---------------- helpers ----------------------------------------------------
__device__ __forceinline__ uint32_t packbf(float x) {
    __nv_bfloat16 h = __float2bfloat16(x);
    float hf = __bfloat162float(h);
    __nv_bfloat16 l = __float2bfloat16(x - hf);
    return ((uint32_t)__bfloat16_as_ushort(h) << 16) | (uint32_t)__bfloat16_as_ushort(l);
}
__device__ __forceinline__ float unpackbf(uint32_t p) {
    return __uint_as_float(p & 0xffff0000u) + __uint_as_float(p << 16);
}
__device__ __forceinline__ uint32_t prmt(uint32_t a, uint32_t b, uint32_t s) {
    uint32_t r; asm("prmt.b32 %0, %1, %2, %3;" : "=r"(r) : "r"(a), "r"(b), "r"(s)); return r;
}

// m16n8k16 bf16 MMA, f32 accumulate (sm_80+ PTX: compiles in both passes).
#define MMA_BF16(c, a, b) \
    asm volatile("mma.sync.aligned.m16n8k16.row.col.f32.bf16.bf16.f32 " \
        "{%0,%1,%2,%3}, {%4,%5,%6,%7}, {%8,%9}, {%0,%1,%2,%3};" \
        : "+f"((c)[0]), "+f"((c)[1]), "+f"((c)[2]), "+f"((c)[3]) \
        : "r"((a)[0]), "r"((a)[1]), "r"((a)[2]), "r"((a)[3]), \
          "r"((b)[0]), "r"((b)[1]))

// ---------------- prep kernels (exactly 3 launches before stage-1) ----------
__global__ void prep_bn_all(const float* g1, const float* b1, const float* m1, const float* v1,
                            const float* g2, const float* b2, const float* m2, const float* v2,
                            const float* g3, const float* b3, const float* m3, const float* v3,
                            float* sc1, float* bi1, float* sc2, float* bi2,
                            float* sc3, float* bi3) {
    int i = blockIdx.x * blockDim.x + threadIdx.x;
    if (i < 256) {
        float inv = g1[i] * rsqrtf(v1[i] + 1e-5f);
        sc1[i] = inv; bi1[i] = b1[i] - m1[i] * inv;
    } else if (i < 512) {
        int c = i - 256;
        float inv = g2[c] * rsqrtf(v2[c] + 1e-5f);
        sc2[c] = inv; bi2[c] = b2[c] - m2[c] * inv;
    } else if (i < 1536) {
        int c = i - 512;
        float inv = g3[c] * rsqrtf(v3[c] + 1e-5f);
        sc3[c] = inv; bi3[c] = b3[c] - m3[c] * inv;
    }
}
__global__ void xprep_kernel(const float* __restrict__ x, uint32_t* __restrict__ xp, int n) {
    int i = blockIdx.x * blockDim.x + threadIdx.x;
    if (i < n) xp[i] = packbf(x[i]);
}
// [Cout][Cin][TAPS] -> packed [oc][tap][ic]
__device__ __forceinline__ void wprep_one(const float* w, uint32_t* wp, int Cin, int TAPS, int i) {
    int ct = Cin * TAPS;
    int oc = i / ct;
    int r  = i - oc * ct;
    int ic = r / TAPS;
    int t  = r - ic * TAPS;
    wp[((size_t)oc * TAPS + t) * Cin + ic] = packbf(w[i]);
}
// ALL weights in one launch (explicit cumulative bounds):
//  ow1: 18,874,368 | ow2: 1,179,648 | ow3: 1,179,648
//  w1:     262,144 | w2:    589,824 | w3:    262,144   total 22,347,776
__global__ void wprep_all(const float* ow1, uint32_t* po1,
                          const float* ow2, uint32_t* po2,
                          const float* ow3, uint32_t* po3,
                          const float* w1,  uint32_t* p1,
                          const float* w2,  uint32_t* p2,
                          const float* w3,  uint32_t* p3) {
    int i = blockIdx.x * blockDim.x + threadIdx.x;
    if (i < 18874368)                 wprep_one(ow1, po1, 1024, 9, i);
    else if (i < 20054016)            wprep_one(ow2, po2, 256, 9, i - 18874368);
    else if (i < 21233664)            wprep_one(ow3, po3, 256, 9, i - 20054016);
    else if (i < 21495808)            wprep_one(w1,  p1, 1024, 1, i - 21233664);
    else if (i < 22085632)            wprep_one(w2,  p2, 256, 9, i - 21495808);
    else if (i < 22347776)            wprep_one(w3,  p3, 256, 1, i - 22085632);
}

// ---------------- fused conv via mma.sync (R11 scalar-LDS mainloop) ----------
// Tile: M=128 oc x N=128 px (2 image rows), K-chunk 64.
// 8 warps: warp w -> (mw=w&3) M-quadrant(32 oc), (nw=w>>2) N-half(64 px).
// Markidis bf16 split: acc += Ahi*Bhi + Ahi*Blo + Alo*Bhi.
// EPI: 0 deform(pack), 1 affine(pack), 2 affine+relu(f32).
static constexpr int DSMEM = 73728;

template<int TAPS, int EPI>
__global__ __launch_bounds__(256)
void mmaconv(const uint32_t* __restrict__ inp, const uint32_t* __restrict__ wp,
             const float* __restrict__ cbias,
             const float* __restrict__ sc, const float* __restrict__ bi,
             uint32_t* __restrict__ outp, float* __restrict__ outf,
             int Cin, int Cout)
{
    extern __shared__ uint32_t sm[];
    uint32_t* Ahi = sm;
    uint32_t* Alo = sm + 4608;
    uint32_t* Bhi = sm + 9216;
    uint32_t* Blo = sm + 13824;

    const int tid  = threadIdx.x;
    const int w    = tid >> 5, lane = tid & 31;
    const int mw   = w & 3, nw = w >> 2;
    const int bimg = blockIdx.x >> 5;
    const int y0   = (blockIdx.x & 31) << 1;
    const int oc0  = blockIdx.y << 7;

    float acc[2][8][4];
#pragma unroll
    for (int a = 0; a < 2; ++a)
#pragma unroll
        for (int b = 0; b < 8; ++b)
#pragma unroll
            for (int c = 0; c < 4; ++c) acc[a][b][c] = 0.f;

    const int n_chunks = TAPS * (Cin >> 6);
    for (int ch = 0; ch < n_chunks; ++ch) {
        const int tap = (TAPS == 9) ? (ch % 9) : 0;
        const int ic0 = ((TAPS == 9) ? (ch / 9) : ch) << 6;
        const int dyt = (TAPS == 9) ? (tap / 3 - 1) : 0;
        const int dxt = (TAPS == 9) ? (tap % 3 - 1) : 0;

        {   // stage A (weights): warp w -> oc rows w*16..+15, lane -> k-pair
            const uint32_t* wrow = wp + ((size_t)(oc0 + (w << 4)) * TAPS + tap) * Cin
                                      + ic0 + (lane << 1);
            const size_t rstride = (size_t)TAPS * Cin;
#pragma unroll 4
            for (int r = 0; r < 16; ++r) {
                uint2 p = *reinterpret_cast<const uint2*>(wrow + (size_t)r * rstride);
                int row = (w << 4) + r;
                Ahi[row * 36 + lane] = prmt(p.x, p.y, 0x7632u);
                Alo[row * 36 + lane] = prmt(p.x, p.y, 0x5410u);
            }
        }
        {   // stage B (pixels): B[n=px][k=ic], coalesced along px
            const uint32_t* ibase = inp + (size_t)bimg * Cin * HWN;
#pragma unroll
            for (int nb = 0; nb < 2; ++nb) {
                const int n  = (w << 4) + (nb << 3) + (lane & 7);
                const int gy = y0 + (n >> 6) + dyt;
                const int gx = (n & 63) + dxt;
                const bool ok = (TAPS == 1) ||
                                (((unsigned)gy < 64u) && ((unsigned)gx < 64u));
                const int gyc = ok ? gy : 0, gxc = ok ? gx : 0;
                const uint32_t* col = ibase + (size_t)(ic0 + ((lane >> 3) << 1)) * HWN
                                            + gyc * 64 + gxc;
#pragma unroll 4
                for (int m = 0; m < 8; ++m) {
                    const uint32_t* q = col + (size_t)(m << 3) * HWN;
                    uint32_t p0 = ok ? q[0]   : 0u;
                    uint32_t p1 = ok ? q[HWN] : 0u;
                    int pair = (lane >> 3) + (m << 2);
                    Bhi[n * 36 + pair] = prmt(p0, p1, 0x7632u);
                    Blo[n * 36 + pair] = prmt(p0, p1, 0x5410u);
                }
            }
        }
        __syncthreads();

#pragma unroll
        for (int ks = 0; ks < 4; ++ks) {
            uint32_t bh[8][2], bl[8][2];
#pragma unroll
            for (int nf = 0; nf < 8; ++nf) {
                int base = (nw * 64 + nf * 8 + (lane >> 2)) * 36 + ks * 8 + (lane & 3);
                bh[nf][0] = Bhi[base];     bh[nf][1] = Bhi[base + 4];
                bl[nf][0] = Blo[base];     bl[nf][1] = Blo[base + 4];
            }
            uint32_t ah[2][4], al[2][4];
#pragma unroll
            for (int mf = 0; mf < 2; ++mf) {
                int base = (mw * 32 + mf * 16 + (lane >> 2)) * 36 + ks * 8 + (lane & 3);
                ah[mf][0] = Ahi[base];       ah[mf][1] = Ahi[base + 288];   // row+8
                ah[mf][2] = Ahi[base + 4];   ah[mf][3] = Ahi[base + 292];
                al[mf][0] = Alo[base];       al[mf][1] = Alo[base + 288];
                al[mf][2] = Alo[base + 4];   al[mf][3] = Alo[base + 292];
            }
#pragma unroll
            for (int mf = 0; mf < 2; ++mf)
#pragma unroll
                for (int nf = 0; nf < 8; ++nf) {
                    MMA_BF16(acc[mf][nf], ah[mf], bh[nf]);
                    MMA_BF16(acc[mf][nf], ah[mf], bl[nf]);
                    MMA_BF16(acc[mf][nf], al[mf], bh[nf]);
                }
        }
        __syncthreads();
    }

    // ---- stage D fragments to SMEM so the epilogue gets a clean (oc,px) view
    float* Ds = (float*)sm;     // [128][130] f32
#pragma unroll
    for (int mf = 0; mf < 2; ++mf)
#pragma unroll
        for (int nf = 0; nf < 8; ++nf) {
            int row = mw * 32 + mf * 16 + (lane >> 2);
            int col = nw * 64 + nf * 8 + 2 * (lane & 3);
            Ds[row * 130 + col]           = acc[mf][nf][0];
            Ds[row * 130 + col + 1]       = acc[mf][nf][1];
            Ds[(row + 8) * 130 + col]     = acc[mf][nf][2];
            Ds[(row + 8) * 130 + col + 1] = acc[mf][nf][3];
        }
    __syncthreads();

    const int tx = tid & 15, ty = tid >> 4;
    float a8[8][8];
#pragma unroll
    for (int i = 0; i < 8; ++i)
#pragma unroll
        for (int j = 0; j < 8; ++j)
            a8[i][j] = Ds[(ty * 8 + i) * 130 + tx * 8 + j];

    if (EPI == 0) {
        const int Cc  = Cout >> 1;
        const int ocb = oc0 + ty * 8;
#pragma unroll
        for (int t2 = 0; t2 < 4; t2++) {
            const int c = (ocb >> 1) + t2;
            const uint32_t* src = inp + (size_t)(bimg * Cin + c) * HWN;
            uint32_t* dst = outp + (size_t)(bimg * Cc + c) * HWN;
            float cby = cbias[ocb + 2 * t2], cbx = cbias[ocb + 2 * t2 + 1];
#pragma unroll
            for (int j = 0; j < 8; j++) {
                int p = tx * 8 + j, gy = y0 + (p >> 6), gx = p & 63;
                float dy = a8[2 * t2][j] + cby;
                float dx = a8[2 * t2 + 1][j] + cbx;
                float py = fminf(fmaxf((float)gy + dy, 0.f), 63.f);
                float px = fminf(fmaxf((float)gx + dx, 0.f), 63.f);
                float fy = floorf(py), fx = floorf(px);
                int iy0 = (int)fy, ix0 = (int)fx;
                int iy1 = min(iy0 + 1, 63), ix1 = min(ix0 + 1, 63);
                float wy = py - fy, wx = px - fx;
                float v00 = unpackbf(src[iy0 * 64 + ix0]), v01 = unpackbf(src[iy0 * 64 + ix1]);
                float v10 = unpackbf(src[iy1 * 64 + ix0]), v11 = unpackbf(src[iy1 * 64 + ix1]);
                float vt = v00 + (v01 - v00) * wx;
                float vb = v10 + (v11 - v10) * wx;
                dst[gy * 64 + gx] = packbf(vt + (vb - vt) * wy);
            }
        }
    } else {
#pragma unroll
        for (int i = 0; i < 8; i++) {
            int oc = oc0 + ty * 8 + i;
            float s = sc[oc], bo = bi[oc];
#pragma unroll
            for (int j = 0; j < 8; j++) {
                int p = tx * 8 + j, gy = y0 + (p >> 6), gx = p & 63;
                float v = a8[i][j] * s + bo;
                size_t o = (size_t)(bimg * Cout + oc) * HWN + gy * 64 + gx;
                if (EPI == 1) outp[o] = packbf(v);
                else          outf[o] = fmaxf(v, 0.f);
            }
        }
    }
}

// ---------------------------------------------------------------------------
extern "C" void kernel_launch(void* const* d_in, const int* in_sizes, int n_in,
                              void* d_out, int out_size)
{
    (void)n_in; (void)out_size;
    const float *x, *ow1, *ob1, *ow2, *ob2, *ow3, *ob3, *w1, *w2, *w3;
    const float *g1, *b1, *m1, *v1, *g2, *b2, *m2, *v2, *g3, *b3, *m3, *v3;
    x   = (const float*)d_in[0];
    ow1 = (const float*)d_in[1];
    ob1 = (const float*)d_in[2];
    if (in_sizes[3] == 262144) {   // signature order
        w1  = (const float*)d_in[3];
        g1  = (const float*)d_in[4];  b1 = (const float*)d_in[5];
        m1  = (const float*)d_in[6];  v1 = (const float*)d_in[7];
        ow2 = (const float*)d_in[8];  ob2 = (const float*)d_in[9];
        w2  = (const float*)d_in[10];
        g2  = (const float*)d_in[11]; b2 = (const float*)d_in[12];
        m2  = (const float*)d_in[13]; v2 = (const float*)d_in[14];
        ow3 = (const float*)d_in[15]; ob3 = (const float*)d_in[16];
        w3  = (const float*)d_in[17];
        g3  = (const float*)d_in[18]; b3 = (const float*)d_in[19];
        m3  = (const float*)d_in[20]; v3 = (const float*)d_in[21];
    } else {                        // setup_inputs dict order
        ow2 = (const float*)d_in[3];  ob2 = (const float*)d_in[4];
        ow3 = (const float*)d_in[5];  ob3 = (const float*)d_in[6];
        w1  = (const float*)d_in[7];
        w2  = (const float*)d_in[8];
        w3  = (const float*)d_in[9];
        g1  = (const float*)d_in[10]; b1 = (const float*)d_in[11];
        m1  = (const float*)d_in[12]; v1 = (const float*)d_in[13];
        g2  = (const float*)d_in[14]; b2 = (const float*)d_in[15];
        m2  = (const float*)d_in[16]; v2 = (const float*)d_in[17];
        g3  = (const float*)d_in[18]; b3 = (const float*)d_in[19];
        m3  = (const float*)d_in[20]; v3 = (const float*)d_in[21];
    }
    float* out = (float*)d_out;

    uint32_t *xp, *h1, *h2, *h3, *h4, *h5, *wo1, *wq1, *wo2, *wq2, *wo3, *wq3;
    float *sc1, *bi1, *sc2, *bi2, *sc3, *bi3;
    cudaGetSymbolAddress((void**)&xp,  g_xp);
    cudaGetSymbolAddress((void**)&h1,  g_h1);
    cudaGetSymbolAddress((void**)&h2,  g_h2);
    cudaGetSymbolAddress((void**)&h3,  g_h3);
    cudaGetSymbolAddress((void**)&h4,  g_h4);
    cudaGetSymbolAddress((void**)&h5,  g_h5);
    cudaGetSymbolAddress((void**)&wo1, g_wo1);
    cudaGetSymbolAddress((void**)&wq1, g_w1);
    cudaGetSymbolAddress((void**)&wo2, g_wo2);
    cudaGetSymbolAddress((void**)&wq2, g_w2);
    cudaGetSymbolAddress((void**)&wo3, g_wo3);
    cudaGetSymbolAddress((void**)&wq3, g_w3);
    cudaGetSymbolAddress((void**)&sc1, g_sc1);
    cudaGetSymbolAddress((void**)&bi1, g_bi1);
    cudaGetSymbolAddress((void**)&sc2, g_sc2);
    cudaGetSymbolAddress((void**)&bi2, g_bi2);
    cudaGetSymbolAddress((void**)&sc3, g_sc3);
    cudaGetSymbolAddress((void**)&bi3, g_bi3);

    cudaFuncSetAttribute(mmaconv<9,0>, cudaFuncAttributeMaxDynamicSharedMemorySize, DSMEM);
    cudaFuncSetAttribute(mmaconv<1,1>, cudaFuncAttributeMaxDynamicSharedMemorySize, DSMEM);
    cudaFuncSetAttribute(mmaconv<9,1>, cudaFuncAttributeMaxDynamicSharedMemorySize, DSMEM);
    cudaFuncSetAttribute(mmaconv<1,2>, cudaFuncAttributeMaxDynamicSharedMemorySize, DSMEM);

    // exactly 3 prep launches -> the 4th launch (which ncu captures) is stage-1
    prep_bn_all<<<6, 256>>>(g1, b1, m1, v1, g2, b2, m2, v2, g3, b3, m3, v3,
                            sc1, bi1, sc2, bi2, sc3, bi3);
    { int n = BBN * 1024 * HWN; xprep_kernel<<<(n + 255) / 256, 256>>>(x, xp, n); }
    { int n = 22347776;
      wprep_all<<<(n + 255) / 256, 256>>>(ow1, wo1, ow2, wo2, ow3, wo3,
                                          w1, wq1, w2, wq2, w3, wq3); }

    const dim3 blk(256);
    mmaconv<9,0><<<dim3(128, 16), blk, DSMEM>>>(xp, wo1, ob1, nullptr, nullptr, h1, nullptr, 1024, 2048);
    mmaconv<1,1><<<dim3(128, 2),  blk, DSMEM>>>(h1, wq1, nullptr, sc1, bi1, h2, nullptr, 1024, 256);
    mmaconv<9,0><<<dim3(128, 4),  blk, DSMEM>>>(h2, wo2, ob2, nullptr, nullptr, h3, nullptr, 256, 512);
    mmaconv<9,1><<<dim3(128, 2),  blk, DSMEM>>>(h3, wq2, nullptr, sc2, bi2, h4, nullptr, 256, 256);
    mmaconv<9,0><<<dim3(128, 4),  blk, DSMEM>>>(h4, wo3, ob3, nullptr, nullptr, h5, nullptr, 256, 512);
    mmaconv<1,2><<<dim3(128, 8),  blk, DSMEM>>>(h5, wq3, nullptr, sc3, bi3, nullptr, out, 256, 1024);
}

// round 16
// speedup vs baseline: 1.5213x; 1.0806x over previous
#include <cuda_runtime.h>
#include <cuda_bf16.h>
#include <cstdint>

#define HWN 4096
#define BBN 4

// ---------------- static scratch (packed {bf16hi,bf16lo} u32) ---------------
__device__ uint32_t g_xp [(size_t)BBN * 1024 * HWN];
__device__ uint32_t g_h1 [(size_t)BBN * 1024 * HWN];
__device__ uint32_t g_h2 [(size_t)BBN * 256  * HWN];
__device__ uint32_t g_h3 [(size_t)BBN * 256  * HWN];
__device__ uint32_t g_h4 [(size_t)BBN * 256  * HWN];
__device__ uint32_t g_h5 [(size_t)BBN * 256  * HWN];
__device__ uint32_t g_wo1[(size_t)2048 * 9 * 1024];
__device__ uint32_t g_w1 [(size_t)256  * 1024];
__device__ uint32_t g_wo2[(size_t)512  * 9 * 256];
__device__ uint32_t g_w2 [(size_t)256  * 9 * 256];
__device__ uint32_t g_wo3[(size_t)512  * 9 * 256];
__device__ uint32_t g_w3 [(size_t)1024 * 256];
__device__ float g_sc1[256],  g_bi1[256];
__device__ float g_sc2[256],  g_bi2[256];
__device__ float g_sc3[1024], g_bi3[1024];

// ---------------- helpers ----------------------------------------------------
__device__ __forceinline__ uint32_t packbf(float x) {
    __nv_bfloat16 h = __float2bfloat16(x);
    float hf = __bfloat162float(h);
    __nv_bfloat16 l = __float2bfloat16(x - hf);
    return ((uint32_t)__bfloat16_as_ushort(h) << 16) | (uint32_t)__bfloat16_as_ushort(l);
}
__device__ __forceinline__ float unpackbf(uint32_t p) {
    return __uint_as_float(p & 0xffff0000u) + __uint_as_float(p << 16);
}
__device__ __forceinline__ uint32_t prmt(uint32_t a, uint32_t b, uint32_t s) {
    uint32_t r; asm("prmt.b32 %0, %1, %2, %3;" : "=r"(r) : "r"(a), "r"(b), "r"(s)); return r;
}

// m16n8k16 bf16 MMA, f32 accumulate (sm_80+ PTX: compiles in both passes).
#define MMA_BF16(c, a, b) \
    asm volatile("mma.sync.aligned.m16n8k16.row.col.f32.bf16.bf16.f32 " \
        "{%0,%1,%2,%3}, {%4,%5,%6,%7}, {%8,%9}, {%0,%1,%2,%3};" \
        : "+f"((c)[0]), "+f"((c)[1]), "+f"((c)[2]), "+f"((c)[3]) \
        : "r"((a)[0]), "r"((a)[1]), "r"((a)[2]), "r"((a)[3]), \
          "r"((b)[0]), "r"((b)[1]))

// ---------------- prep kernels (exactly 3 launches before stage-1) ----------
__global__ void prep_bn_all(const float* g1, const float* b1, const float* m1, const float* v1,
                            const float* g2, const float* b2, const float* m2, const float* v2,
                            const float* g3, const float* b3, const float* m3, const float* v3,
                            float* sc1, float* bi1, float* sc2, float* bi2,
                            float* sc3, float* bi3) {
    int i = blockIdx.x * blockDim.x + threadIdx.x;
    if (i < 256) {
        float inv = g1[i] * rsqrtf(v1[i] + 1e-5f);
        sc1[i] = inv; bi1[i] = b1[i] - m1[i] * inv;
    } else if (i < 512) {
        int c = i - 256;
        float inv = g2[c] * rsqrtf(v2[c] + 1e-5f);
        sc2[c] = inv; bi2[c] = b2[c] - m2[c] * inv;
    } else if (i < 1536) {
        int c = i - 512;
        float inv = g3[c] * rsqrtf(v3[c] + 1e-5f);
        sc3[c] = inv; bi3[c] = b3[c] - m3[c] * inv;
    }
}
__global__ void xprep_kernel(const float* __restrict__ x, uint32_t* __restrict__ xp, int n) {
    int i = blockIdx.x * blockDim.x + threadIdx.x;
    if (i < n) xp[i] = packbf(x[i]);
}
__device__ __forceinline__ void wprep_one(const float* w, uint32_t* wp, int Cin, int TAPS, int i) {
    int ct = Cin * TAPS;
    int oc = i / ct;
    int r  = i - oc * ct;
    int ic = r / TAPS;
    int t  = r - ic * TAPS;
    wp[((size_t)oc * TAPS + t) * Cin + ic] = packbf(w[i]);
}
__global__ void wprep_all(const float* ow1, uint32_t* po1,
                          const float* ow2, uint32_t* po2,
                          const float* ow3, uint32_t* po3,
                          const float* w1,  uint32_t* p1,
                          const float* w2,  uint32_t* p2,
                          const float* w3,  uint32_t* p3) {
    int i = blockIdx.x * blockDim.x + threadIdx.x;
    if (i < 18874368)                 wprep_one(ow1, po1, 1024, 9, i);
    else if (i < 20054016)            wprep_one(ow2, po2, 256, 9, i - 18874368);
    else if (i < 21233664)            wprep_one(ow3, po3, 256, 9, i - 20054016);
    else if (i < 21495808)            wprep_one(w1,  p1, 1024, 1, i - 21233664);
    else if (i < 22085632)            wprep_one(w2,  p2, 256, 9, i - 21495808);
    else if (i < 22347776)            wprep_one(w3,  p3, 256, 1, i - 22085632);
}

// ---------------- fused conv via mma.sync, software-pipelined ----------------
// Tile: M=128 oc x N=128 px, K-chunk 64. 8 warps (mw=w&3, nw=w>>2).
// Double-buffered SMEM tiles (2 x 72KB); gmem prefetch of chunk ch+1 into
// registers overlaps the MMA stream of chunk ch; ONE barrier per chunk.
// Markidis bf16 split: acc += Ahi*Bhi + Ahi*Blo + Alo*Bhi.
// EPI: 0 deform(pack), 1 affine(pack), 2 affine+relu(f32).
static constexpr int TILE_W = 18432;   // words per buffer (4 x 4608)
static constexpr int DSMEM  = 147456;  // 2 buffers

template<int TAPS, int EPI>
__global__ __launch_bounds__(256)
void mmaconv(const uint32_t* __restrict__ inp, const uint32_t* __restrict__ wp,
             const float* __restrict__ cbias,
             const float* __restrict__ sc, const float* __restrict__ bi,
             uint32_t* __restrict__ outp, float* __restrict__ outf,
             int Cin, int Cout)
{
    extern __shared__ uint32_t sm[];

    const int tid  = threadIdx.x;
    const int w    = tid >> 5, lane = tid & 31;
    const int mw   = w & 3, nw = w >> 2;
    const int bimg = blockIdx.x >> 5;
    const int y0   = (blockIdx.x & 31) << 1;
    const int oc0  = blockIdx.y << 7;

    // prefetch registers
    uint2    pa[16];
    uint32_t pb0[16], pb1[16];

    // ---- chunk gmem prefetch into registers --------------------------------
    auto chunk_prefetch = [&](int ch) {
        const int tap = (TAPS == 9) ? (ch % 9) : 0;
        const int ic0 = ((TAPS == 9) ? (ch / 9) : ch) << 6;
        const int dyt = (TAPS == 9) ? (tap / 3 - 1) : 0;
        const int dxt = (TAPS == 9) ? (tap % 3 - 1) : 0;
        {   // A: warp w -> oc rows w*16..+15, lane -> k-pair
            const uint32_t* wrow = wp + ((size_t)(oc0 + (w << 4)) * TAPS + tap) * Cin
                                      + ic0 + (lane << 1);
            const size_t rstride = (size_t)TAPS * Cin;
#pragma unroll
            for (int r = 0; r < 16; ++r)
                pa[r] = *reinterpret_cast<const uint2*>(wrow + (size_t)r * rstride);
        }
        {   // B: warp w -> pixel rows w*16..+15
            const uint32_t* ibase = inp + (size_t)bimg * Cin * HWN;
#pragma unroll
            for (int nb = 0; nb < 2; ++nb) {
                const int n  = (w << 4) + (nb << 3) + (lane & 7);
                const int gy = y0 + (n >> 6) + dyt;
                const int gx = (n & 63) + dxt;
                const bool ok = (TAPS == 1) ||
                                (((unsigned)gy < 64u) && ((unsigned)gx < 64u));
                const int gyc = ok ? gy : 0, gxc = ok ? gx : 0;
                const uint32_t* col = ibase + (size_t)(ic0 + ((lane >> 3) << 1)) * HWN
                                            + gyc * 64 + gxc;
#pragma unroll
                for (int m = 0; m < 8; ++m) {
                    const uint32_t* q = col + (size_t)(m << 3) * HWN;
                    pb0[nb * 8 + m] = ok ? q[0]   : 0u;
                    pb1[nb * 8 + m] = ok ? q[HWN] : 0u;
                }
            }
        }
    };

    // ---- registers -> SMEM tiles (chunk-independent layout) ----------------
    auto tiles_sts = [&](uint32_t bo) {
        uint32_t* Ahi = sm + bo;
        uint32_t* Alo = sm + bo + 4608;
        uint32_t* Bhi = sm + bo + 9216;
        uint32_t* Blo = sm + bo + 13824;
#pragma unroll
        for (int r = 0; r < 16; ++r) {
            int row = (w << 4) + r;
            Ahi[row * 36 + lane] = prmt(pa[r].x, pa[r].y, 0x7632u);
            Alo[row * 36 + lane] = prmt(pa[r].x, pa[r].y, 0x5410u);
        }
#pragma unroll
        for (int nb = 0; nb < 2; ++nb) {
            const int n = (w << 4) + (nb << 3) + (lane & 7);
#pragma unroll
            for (int m = 0; m < 8; ++m) {
                int pair = (lane >> 3) + (m << 2);
                uint32_t p0 = pb0[nb * 8 + m], p1 = pb1[nb * 8 + m];
                Bhi[n * 36 + pair] = prmt(p0, p1, 0x7632u);
                Blo[n * 36 + pair] = prmt(p0, p1, 0x5410u);
            }
        }
    };

    float acc[2][8][4];
#pragma unroll
    for (int a = 0; a < 2; ++a)
#pragma unroll
        for (int b = 0; b < 8; ++b)
#pragma unroll
            for (int c = 0; c < 4; ++c) acc[a][b][c] = 0.f;

    // ---- MMA stream on one buffer ------------------------------------------
    auto tiles_mma = [&](uint32_t bo) {
        uint32_t* Ahi = sm + bo;
        uint32_t* Alo = sm + bo + 4608;
        uint32_t* Bhi = sm + bo + 9216;
        uint32_t* Blo = sm + bo + 13824;
#pragma unroll
        for (int ks = 0; ks < 4; ++ks) {
            uint32_t bh[8][2], bl[8][2];
#pragma unroll
            for (int nf = 0; nf < 8; ++nf) {
                int base = (nw * 64 + nf * 8 + (lane >> 2)) * 36 + ks * 8 + (lane & 3);
                bh[nf][0] = Bhi[base];     bh[nf][1] = Bhi[base + 4];
                bl[nf][0] = Blo[base];     bl[nf][1] = Blo[base + 4];
            }
            uint32_t ah[2][4], al[2][4];
#pragma unroll
            for (int mf = 0; mf < 2; ++mf) {
                int base = (mw * 32 + mf * 16 + (lane >> 2)) * 36 + ks * 8 + (lane & 3);
                ah[mf][0] = Ahi[base];       ah[mf][1] = Ahi[base + 288];
                ah[mf][2] = Ahi[base + 4];   ah[mf][3] = Ahi[base + 292];
                al[mf][0] = Alo[base];       al[mf][1] = Alo[base + 288];
                al[mf][2] = Alo[base + 4];   al[mf][3] = Alo[base + 292];
            }
#pragma unroll
            for (int mf = 0; mf < 2; ++mf)
#pragma unroll
                for (int nf = 0; nf < 8; ++nf) {
                    MMA_BF16(acc[mf][nf], ah[mf], bh[nf]);
                    MMA_BF16(acc[mf][nf], ah[mf], bl[nf]);
                    MMA_BF16(acc[mf][nf], al[mf], bh[nf]);
                }
        }
    };

    // ---- pipelined mainloop -------------------------------------------------
    const int n_chunks = TAPS * (Cin >> 6);
    chunk_prefetch(0);
    tiles_sts(0);
    __syncthreads();
    for (int ch = 0; ch < n_chunks; ++ch) {
        const int nxt = ch + 1;
        if (nxt < n_chunks) chunk_prefetch(nxt);     // LDGs overlap MMA below
        tiles_mma((uint32_t)(ch & 1) * TILE_W);
        if (nxt < n_chunks) tiles_sts((uint32_t)(nxt & 1) * TILE_W);
        __syncthreads();
    }

    // ---- stage D fragments to SMEM so the epilogue gets a clean (oc,px) view
    float* Ds = (float*)sm;     // [128][130] f32 (66.5KB, fits buffer region)
#pragma unroll
    for (int mf = 0; mf < 2; ++mf)
#pragma unroll
        for (int nf = 0; nf < 8; ++nf) {
            int row = mw * 32 + mf * 16 + (lane >> 2);
            int col = nw * 64 + nf * 8 + 2 * (lane & 3);
            Ds[row * 130 + col]           = acc[mf][nf][0];
            Ds[row * 130 + col + 1]       = acc[mf][nf][1];
            Ds[(row + 8) * 130 + col]     = acc[mf][nf][2];
            Ds[(row + 8) * 130 + col + 1] = acc[mf][nf][3];
        }
    __syncthreads();

    const int tx = tid & 15, ty = tid >> 4;
    float a8[8][8];
#pragma unroll
    for (int i = 0; i < 8; ++i)
#pragma unroll
        for (int j = 0; j < 8; ++j)
            a8[i][j] = Ds[(ty * 8 + i) * 130 + tx * 8 + j];

    if (EPI == 0) {
        const int Cc  = Cout >> 1;
        const int ocb = oc0 + ty * 8;
#pragma unroll
        for (int t2 = 0; t2 < 4; t2++) {
            const int c = (ocb >> 1) + t2;
            const uint32_t* src = inp + (size_t)(bimg * Cin + c) * HWN;
            uint32_t* dst = outp + (size_t)(bimg * Cc + c) * HWN;
            float cby = cbias[ocb + 2 * t2], cbx = cbias[ocb + 2 * t2 + 1];
#pragma unroll
            for (int j = 0; j < 8; j++) {
                int p = tx * 8 + j, gy = y0 + (p >> 6), gx = p & 63;
                float dy = a8[2 * t2][j] + cby;
                float dx = a8[2 * t2 + 1][j] + cbx;
                float py = fminf(fmaxf((float)gy + dy, 0.f), 63.f);
                float px = fminf(fmaxf((float)gx + dx, 0.f), 63.f);
                float fy = floorf(py), fx = floorf(px);
                int iy0 = (int)fy, ix0 = (int)fx;
                int iy1 = min(iy0 + 1, 63), ix1 = min(ix0 + 1, 63);
                float wy = py - fy, wx = px - fx;
                float v00 = unpackbf(src[iy0 * 64 + ix0]), v01 = unpackbf(src[iy0 * 64 + ix1]);
                float v10 = unpackbf(src[iy1 * 64 + ix0]), v11 = unpackbf(src[iy1 * 64 + ix1]);
                float vt = v00 + (v01 - v00) * wx;
                float vb = v10 + (v11 - v10) * wx;
                dst[gy * 64 + gx] = packbf(vt + (vb - vt) * wy);
            }
        }
    } else {
#pragma unroll
        for (int i = 0; i < 8; i++) {
            int oc = oc0 + ty * 8 + i;
            float s = sc[oc], bo = bi[oc];
#pragma unroll
            for (int j = 0; j < 8; j++) {
                int p = tx * 8 + j, gy = y0 + (p >> 6), gx = p & 63;
                float v = a8[i][j] * s + bo;
                size_t o = (size_t)(bimg * Cout + oc) * HWN + gy * 64 + gx;
                if (EPI == 1) outp[o] = packbf(v);
                else          outf[o] = fmaxf(v, 0.f);
            }
        }
    }
}

// ---------------------------------------------------------------------------
extern "C" void kernel_launch(void* const* d_in, const int* in_sizes, int n_in,
                              void* d_out, int out_size)
{
    (void)n_in; (void)out_size;
    const float *x, *ow1, *ob1, *ow2, *ob2, *ow3, *ob3, *w1, *w2, *w3;
    const float *g1, *b1, *m1, *v1, *g2, *b2, *m2, *v2, *g3, *b3, *m3, *v3;
    x   = (const float*)d_in[0];
    ow1 = (const float*)d_in[1];
    ob1 = (const float*)d_in[2];
    if (in_sizes[3] == 262144) {   // signature order
        w1  = (const float*)d_in[3];
        g1  = (const float*)d_in[4];  b1 = (const float*)d_in[5];
        m1  = (const float*)d_in[6];  v1 = (const float*)d_in[7];
        ow2 = (const float*)d_in[8];  ob2 = (const float*)d_in[9];
        w2  = (const float*)d_in[10];
        g2  = (const float*)d_in[11]; b2 = (const float*)d_in[12];
        m2  = (const float*)d_in[13]; v2 = (const float*)d_in[14];
        ow3 = (const float*)d_in[15]; ob3 = (const float*)d_in[16];
        w3  = (const float*)d_in[17];
        g3  = (const float*)d_in[18]; b3 = (const float*)d_in[19];
        m3  = (const float*)d_in[20]; v3 = (const float*)d_in[21];
    } else {                        // setup_inputs dict order
        ow2 = (const float*)d_in[3];  ob2 = (const float*)d_in[4];
        ow3 = (const float*)d_in[5];  ob3 = (const float*)d_in[6];
        w1  = (const float*)d_in[7];
        w2  = (const float*)d_in[8];
        w3  = (const float*)d_in[9];
        g1  = (const float*)d_in[10]; b1 = (const float*)d_in[11];
        m1  = (const float*)d_in[12]; v1 = (const float*)d_in[13];
        g2  = (const float*)d_in[14]; b2 = (const float*)d_in[15];
        m2  = (const float*)d_in[16]; v2 = (const float*)d_in[17];
        g3  = (const float*)d_in[18]; b3 = (const float*)d_in[19];
        m3  = (const float*)d_in[20]; v3 = (const float*)d_in[21];
    }
    float* out = (float*)d_out;

    uint32_t *xp, *h1, *h2, *h3, *h4, *h5, *wo1, *wq1, *wo2, *wq2, *wo3, *wq3;
    float *sc1, *bi1, *sc2, *bi2, *sc3, *bi3;
    cudaGetSymbolAddress((void**)&xp,  g_xp);
    cudaGetSymbolAddress((void**)&h1,  g_h1);
    cudaGetSymbolAddress((void**)&h2,  g_h2);
    cudaGetSymbolAddress((void**)&h3,  g_h3);
    cudaGetSymbolAddress((void**)&h4,  g_h4);
    cudaGetSymbolAddress((void**)&h5,  g_h5);
    cudaGetSymbolAddress((void**)&wo1, g_wo1);
    cudaGetSymbolAddress((void**)&wq1, g_w1);
    cudaGetSymbolAddress((void**)&wo2, g_wo2);
    cudaGetSymbolAddress((void**)&wq2, g_w2);
    cudaGetSymbolAddress((void**)&wo3, g_wo3);
    cudaGetSymbolAddress((void**)&wq3, g_w3);
    cudaGetSymbolAddress((void**)&sc1, g_sc1);
    cudaGetSymbolAddress((void**)&bi1, g_bi1);
    cudaGetSymbolAddress((void**)&sc2, g_sc2);
    cudaGetSymbolAddress((void**)&bi2, g_bi2);
    cudaGetSymbolAddress((void**)&sc3, g_sc3);
    cudaGetSymbolAddress((void**)&bi3, g_bi3);

    cudaFuncSetAttribute(mmaconv<9,0>, cudaFuncAttributeMaxDynamicSharedMemorySize, DSMEM);
    cudaFuncSetAttribute(mmaconv<1,1>, cudaFuncAttributeMaxDynamicSharedMemorySize, DSMEM);
    cudaFuncSetAttribute(mmaconv<9,1>, cudaFuncAttributeMaxDynamicSharedMemorySize, DSMEM);
    cudaFuncSetAttribute(mmaconv<1,2>, cudaFuncAttributeMaxDynamicSharedMemorySize, DSMEM);

    // exactly 3 prep launches -> the 4th launch (which ncu captures) is stage-1
    prep_bn_all<<<6, 256>>>(g1, b1, m1, v1, g2, b2, m2, v2, g3, b3, m3, v3,
                            sc1, bi1, sc2, bi2, sc3, bi3);
    { int n = BBN * 1024 * HWN; xprep_kernel<<<(n + 255) / 256, 256>>>(x, xp, n); }
    { int n = 22347776;
      wprep_all<<<(n + 255) / 256, 256>>>(ow1, wo1, ow2, wo2, ow3, wo3,
                                          w1, wq1, w2, wq2, w3, wq3); }

    const dim3 blk(256);
    mmaconv<9,0><<<dim3(128, 16), blk, DSMEM>>>(xp, wo1, ob1, nullptr, nullptr, h1, nullptr, 1024, 2048);
    mmaconv<1,1><<<dim3(128, 2),  blk, DSMEM>>>(h1, wq1, nullptr, sc1, bi1, h2, nullptr, 1024, 256);
    mmaconv<9,0><<<dim3(128, 4),  blk, DSMEM>>>(h2, wo2, ob2, nullptr, nullptr, h3, nullptr, 256, 512);
    mmaconv<9,1><<<dim3(128, 2),  blk, DSMEM>>>(h3, wq2, nullptr, sc2, bi2, h4, nullptr, 256, 256);
    mmaconv<9,0><<<dim3(128, 4),  blk, DSMEM>>>(h4, wo3, ob3, nullptr, nullptr, h5, nullptr, 256, 512);
    mmaconv<1,2><<<dim3(128, 8),  blk, DSMEM>>>(h5, wq3, nullptr, sc3, bi3, nullptr, out, 256, 1024);
}